// round 13
// baseline (speedup 1.0000x reference)
#include <cuda_runtime.h>

#define N_NODES 100000
#define N_EDGES 1600000

// ---------------- scratch (static __device__, no allocations) ----------------
__device__ int   g_deg[N_NODES];
__device__ int   g_rowptr[N_NODES + 1];
__device__ int   g_cursor[N_NODES];
__device__ int   g_col[N_EDGES];
__device__ float g_agg [(size_t)N_NODES * 256];
__device__ float g_bufA[(size_t)N_NODES * 256];
__device__ float g_bufB[(size_t)N_NODES * 256];
__device__ float g_stats[1152];   // [0..fout) = sum, [fout..2fout) = sumsq

// ---------------- CSR build ----------------
__global__ void k_zero_deg() {
    int i = blockIdx.x * blockDim.x + threadIdx.x;
    if (i < N_NODES) g_deg[i] = 0;
}

__global__ void k_count_deg(const int* __restrict__ dst) {
    int e = blockIdx.x * blockDim.x + threadIdx.x;
    if (e < N_EDGES) atomicAdd(&g_deg[dst[e]], 1);
}

// single-block exclusive scan of g_deg -> g_rowptr (+cursor copy)
__global__ void k_scan_deg() {
    __shared__ int sm[1024];
    __shared__ int carry;
    if (threadIdx.x == 0) carry = 0;
    __syncthreads();
    for (int base = 0; base < N_NODES; base += 1024) {
        int i = base + threadIdx.x;
        int v = (i < N_NODES) ? g_deg[i] : 0;
        sm[threadIdx.x] = v;
        __syncthreads();
        #pragma unroll
        for (int off = 1; off < 1024; off <<= 1) {
            int t = 0;
            if (threadIdx.x >= off) t = sm[threadIdx.x - off];
            __syncthreads();
            if (threadIdx.x >= off) sm[threadIdx.x] += t;
            __syncthreads();
        }
        int incl = sm[threadIdx.x];
        int excl = incl - v + carry;
        if (i < N_NODES) { g_rowptr[i] = excl; g_cursor[i] = excl; }
        __syncthreads();
        if (threadIdx.x == 1023) carry += sm[1023];
        __syncthreads();
    }
    if (threadIdx.x == 0) g_rowptr[N_NODES] = carry;
}

__global__ void k_fill_csr(const int* __restrict__ src, const int* __restrict__ dst) {
    int e = blockIdx.x * blockDim.x + threadIdx.x;
    if (e < N_EDGES) {
        int d = dst[e];
        int p = atomicAdd(&g_cursor[d], 1);
        g_col[p] = src[e];
    }
}

// ---------------- SpMM (mean aggregation), warp per node ----------------
template <int FIN>
__global__ void k_spmm_mean(const float* __restrict__ x) {
    int warp = (blockIdx.x * blockDim.x + threadIdx.x) >> 5;
    if (warp >= N_NODES) return;
    int lane = threadIdx.x & 31;
    int s = g_rowptr[warp];
    int e = g_rowptr[warp + 1];
    constexpr int NK = (FIN + 31) / 32;
    float acc[NK];
    #pragma unroll
    for (int k = 0; k < NK; k++) acc[k] = 0.f;

    int j = s;
    for (; j + 1 < e; j += 2) {
        int s0 = g_col[j];
        int s1 = g_col[j + 1];
        const float* r0 = x + (size_t)s0 * FIN;
        const float* r1 = x + (size_t)s1 * FIN;
        #pragma unroll
        for (int k = 0; k < NK; k++) {
            int c = k * 32 + lane;
            if (c < FIN) acc[k] += __ldg(r0 + c) + __ldg(r1 + c);
        }
    }
    if (j < e) {
        int s0 = g_col[j];
        const float* r0 = x + (size_t)s0 * FIN;
        #pragma unroll
        for (int k = 0; k < NK; k++) {
            int c = k * 32 + lane;
            if (c < FIN) acc[k] += __ldg(r0 + c);
        }
    }
    int d = e - s;
    float inv = 1.0f / (float)(d > 0 ? d : 1);
    float* out = g_agg + (size_t)warp * FIN;
    #pragma unroll
    for (int k = 0; k < NK; k++) {
        int c = k * 32 + lane;
        if (c < FIN) out[c] = acc[k] * inv;
    }
}

// ---------------- fused dual GEMM: out = A1*B1^T + A2*B2^T + bias ----------------
// A1 = agg [M,K], A2 = x [M,K], B1 = Wl [fout,K], B2 = Wr [fout,K] (row-major)
// block tile 128x64, thread tile 8x8, BK=16, 128 threads
template <int K>
__launch_bounds__(128, 4)
__global__ void k_gemm_dual(const float* __restrict__ A1, const float* __restrict__ A2,
                            const float* __restrict__ B1, const float* __restrict__ B2,
                            const float* __restrict__ bias, float* __restrict__ out,
                            int fout) {
    constexpr int BM = 128, BN = 64, BK = 16;
    constexpr int K2 = 2 * K;
    constexpr int NT = (K2 + BK - 1) / BK;
    constexpr int AST = BK + 4;   // 20 floats, keeps float4 alignment, kills store conflicts
    constexpr int BST = BN + 4;   // 68 floats

    __shared__ float As[BM * AST];
    __shared__ float Bs[BK * BST];

    int tid = threadIdx.x;
    int tx = tid & 7;     // col group: cols tx*8 .. tx*8+7
    int ty = tid >> 3;    // row group: rows ty*8 .. ty*8+7
    int m0 = blockIdx.x * BM;
    int n0 = blockIdx.y * BN;

    float4 pa[4];
    float4 pb[2];

    // A tile: 128 rows x 16 k = 512 float4; thread handles 4 (idx = tid + i*128)
    //   c = idx & 3 (k-offset 4c), m = idx >> 2
    // B tile: 64 rows x 16 k = 256 float4; thread handles 2
    auto loadA = [&](int kt) {
        int kbase = kt * BK;
        #pragma unroll
        for (int i = 0; i < 4; i++) {
            int idx = tid + i * 128;
            int c = idx & 3, m = idx >> 2;
            int k2 = kbase + c * 4;
            float4 v = make_float4(0.f, 0.f, 0.f, 0.f);
            int row = m0 + m;
            if (row < N_NODES && k2 < K2) {
                const float* srcp = (k2 < K) ? (A1 + (size_t)row * K + k2)
                                             : (A2 + (size_t)row * K + (k2 - K));
                v = *(const float4*)srcp;
            }
            pa[i] = v;
        }
    };
    auto loadB = [&](int kt) {
        int kbase = kt * BK;
        #pragma unroll
        for (int i = 0; i < 2; i++) {
            int idx = tid + i * 128;
            int c = idx & 3, o = idx >> 2;
            int k2 = kbase + c * 4;
            float4 v = make_float4(0.f, 0.f, 0.f, 0.f);
            if (k2 < K2) {
                int on = n0 + o;
                const float* srcp = (k2 < K) ? (B1 + (size_t)on * K + k2)
                                             : (B2 + (size_t)on * K + (k2 - K));
                v = *(const float4*)srcp;
            }
            pb[i] = v;
        }
    };
    auto storeA = [&]() {
        #pragma unroll
        for (int i = 0; i < 4; i++) {
            int idx = tid + i * 128;
            int c = idx & 3, m = idx >> 2;
            *(float4*)&As[m * AST + c * 4] = pa[i];
        }
    };
    auto storeB = [&]() {
        #pragma unroll
        for (int i = 0; i < 2; i++) {
            int idx = tid + i * 128;
            int c = idx & 3, o = idx >> 2;
            float v[4] = {pb[i].x, pb[i].y, pb[i].z, pb[i].w};
            #pragma unroll
            for (int q = 0; q < 4; q++) Bs[(c * 4 + q) * BST + o] = v[q];
        }
    };

    float acc[8][8];
    #pragma unroll
    for (int i = 0; i < 8; i++)
        #pragma unroll
        for (int j = 0; j < 8; j++) acc[i][j] = 0.f;

    loadA(0);
    loadB(0);
    for (int kt = 0; kt < NT; kt++) {
        __syncthreads();
        storeA();
        storeB();
        __syncthreads();
        if (kt + 1 < NT) { loadA(kt + 1); loadB(kt + 1); }
        #pragma unroll
        for (int kk = 0; kk < BK; kk++) {
            float a[8], b[8];
            #pragma unroll
            for (int i = 0; i < 8; i++) a[i] = As[(ty * 8 + i) * AST + kk];
            float4 b0 = *(float4*)&Bs[kk * BST + tx * 8];
            float4 b1 = *(float4*)&Bs[kk * BST + tx * 8 + 4];
            b[0] = b0.x; b[1] = b0.y; b[2] = b0.z; b[3] = b0.w;
            b[4] = b1.x; b[5] = b1.y; b[6] = b1.z; b[7] = b1.w;
            #pragma unroll
            for (int i = 0; i < 8; i++)
                #pragma unroll
                for (int j = 0; j < 8; j++)
                    acc[i][j] = fmaf(a[i], b[j], acc[i][j]);
        }
    }

    float bv[8];
    #pragma unroll
    for (int j = 0; j < 8; j++) bv[j] = bias[n0 + tx * 8 + j];

    #pragma unroll
    for (int i = 0; i < 8; i++) {
        int m = m0 + ty * 8 + i;
        if (m < N_NODES) {
            float* orow = out + (size_t)m * fout + n0 + tx * 8;
            float4 o0 = make_float4(acc[i][0] + bv[0], acc[i][1] + bv[1],
                                    acc[i][2] + bv[2], acc[i][3] + bv[3]);
            float4 o1 = make_float4(acc[i][4] + bv[4], acc[i][5] + bv[5],
                                    acc[i][6] + bv[6], acc[i][7] + bv[7]);
            *(float4*)orow = o0;
            *(float4*)(orow + 4) = o1;
        }
    }
}

// ---------------- BatchNorm ----------------
__global__ void k_zero_stats(int n2) {
    int i = blockIdx.x * blockDim.x + threadIdx.x;
    if (i < n2) g_stats[i] = 0.f;
}

__global__ void k_bn_reduce(const float* __restrict__ X, int fout) {
    __shared__ float s1[256], s2[256];
    int c = threadIdx.x & 63;
    int r = threadIdx.x >> 6;
    int col = blockIdx.y * 64 + c;
    float sum = 0.f, sq = 0.f;
    for (int m = blockIdx.x * 4 + r; m < N_NODES; m += gridDim.x * 4) {
        float v = X[(size_t)m * fout + col];
        sum += v;
        sq = fmaf(v, v, sq);
    }
    s1[threadIdx.x] = sum;
    s2[threadIdx.x] = sq;
    __syncthreads();
    if (r == 0) {
        sum = s1[c] + s1[c + 64] + s1[c + 128] + s1[c + 192];
        sq  = s2[c] + s2[c + 64] + s2[c + 128] + s2[c + 192];
        atomicAdd(&g_stats[col], sum);
        atomicAdd(&g_stats[fout + col], sq);
    }
}

// fout is a power of two (64/128/256) for all BN layers
__global__ void k_bn_apply(float* __restrict__ X, const float* __restrict__ gamma,
                           const float* __restrict__ beta, int fout) {
    const float invN = 1.0f / (float)N_NODES;
    int idx4 = blockIdx.x * blockDim.x + threadIdx.x;
    int total4 = N_NODES * fout / 4;
    if (idx4 >= total4) return;
    int c0 = (idx4 * 4) & (fout - 1);
    float4 v = *(float4*)(X + (size_t)idx4 * 4);
    float vv[4] = {v.x, v.y, v.z, v.w};
    #pragma unroll
    for (int q = 0; q < 4; q++) {
        int c = c0 + q;
        float m = g_stats[c] * invN;
        float var = g_stats[fout + c] * invN - m * m;
        float sc = rsqrtf(var + 1e-5f) * gamma[c];
        float y = (vv[q] - m) * sc + beta[c];
        vv[q] = fmaxf(y, 0.f);
    }
    *(float4*)(X + (size_t)idx4 * 4) = make_float4(vv[0], vv[1], vv[2], vv[3]);
}

// ---------------- driver ----------------
extern "C" void kernel_launch(void* const* d_in, const int* in_sizes, int n_in,
                              void* d_out, int out_size) {
    const float* x0  = (const float*)d_in[0];
    const int*   ei  = (const int*)d_in[1];
    const int*   srcp = ei;
    const int*   dstp = ei + N_EDGES;

    const float* Wl[5] = {(const float*)d_in[2], (const float*)d_in[5], (const float*)d_in[8],
                          (const float*)d_in[11], (const float*)d_in[14]};
    const float* Wr[5] = {(const float*)d_in[3], (const float*)d_in[6], (const float*)d_in[9],
                          (const float*)d_in[12], (const float*)d_in[15]};
    const float* bs[5] = {(const float*)d_in[4], (const float*)d_in[7], (const float*)d_in[10],
                          (const float*)d_in[13], (const float*)d_in[16]};
    const float* gm[4] = {(const float*)d_in[17], (const float*)d_in[19],
                          (const float*)d_in[21], (const float*)d_in[23]};
    const float* be[4] = {(const float*)d_in[18], (const float*)d_in[20],
                          (const float*)d_in[22], (const float*)d_in[24]};

    float *agg, *bufA, *bufB;
    cudaGetSymbolAddress((void**)&agg,  g_agg);
    cudaGetSymbolAddress((void**)&bufA, g_bufA);
    cudaGetSymbolAddress((void**)&bufB, g_bufB);
    float* outp = (float*)d_out;

    // ---- CSR build ----
    k_zero_deg<<<(N_NODES + 255) / 256, 256>>>();
    k_count_deg<<<(N_EDGES + 255) / 256, 256>>>(dstp);
    k_scan_deg<<<1, 1024>>>();
    k_fill_csr<<<(N_EDGES + 255) / 256, 256>>>(srcp, dstp);

    const int SPMM_BLOCKS = (N_NODES * 32 + 255) / 256;   // warp per node, 8 warps/block
    const int GX = (N_NODES + 127) / 128;

    // ---- layer 1: 196 -> 64 ----
    k_spmm_mean<196><<<SPMM_BLOCKS, 256>>>(x0);
    k_gemm_dual<196><<<dim3(GX, 1), 128>>>(agg, x0, Wl[0], Wr[0], bs[0], bufA, 64);
    k_zero_stats<<<1, 512>>>(128);
    k_bn_reduce<<<dim3(256, 1), 256>>>(bufA, 64);
    k_bn_apply<<<(N_NODES * 64 / 4 + 255) / 256, 256>>>(bufA, gm[0], be[0], 64);

    // ---- layer 2: 64 -> 128 ----
    k_spmm_mean<64><<<SPMM_BLOCKS, 256>>>(bufA);
    k_gemm_dual<64><<<dim3(GX, 2), 128>>>(agg, bufA, Wl[1], Wr[1], bs[1], bufB, 128);
    k_zero_stats<<<1, 512>>>(256);
    k_bn_reduce<<<dim3(256, 2), 256>>>(bufB, 128);
    k_bn_apply<<<(N_NODES * 128 / 4 + 255) / 256, 256>>>(bufB, gm[1], be[1], 128);

    // ---- layer 3: 128 -> 256 ----
    k_spmm_mean<128><<<SPMM_BLOCKS, 256>>>(bufB);
    k_gemm_dual<128><<<dim3(GX, 4), 128>>>(agg, bufB, Wl[2], Wr[2], bs[2], bufA, 256);
    k_zero_stats<<<1, 512>>>(512);
    k_bn_reduce<<<dim3(256, 4), 256>>>(bufA, 256);
    k_bn_apply<<<(N_NODES * 256 / 4 + 255) / 256, 256>>>(bufA, gm[2], be[2], 256);

    // ---- layer 4: 256 -> 256 ----
    k_spmm_mean<256><<<SPMM_BLOCKS, 256>>>(bufA);
    k_gemm_dual<256><<<dim3(GX, 4), 128>>>(agg, bufA, Wl[3], Wr[3], bs[3], bufB, 256);
    k_zero_stats<<<1, 512>>>(512);
    k_bn_reduce<<<dim3(256, 4), 256>>>(bufB, 256);
    k_bn_apply<<<(N_NODES * 256 / 4 + 255) / 256, 256>>>(bufB, gm[3], be[3], 256);

    // ---- layer 5: 256 -> 576 (no BN/relu), write to d_out ----
    k_spmm_mean<256><<<SPMM_BLOCKS, 256>>>(bufB);
    k_gemm_dual<256><<<dim3(GX, 9), 128>>>(agg, bufB, Wl[4], Wr[4], bs[4], outp, 576);
}

// round 14
// speedup vs baseline: 1.0022x; 1.0022x over previous
#include <cuda_runtime.h>

#define N_NODES 100000
#define N_EDGES 1600000

// ---------------- scratch (static __device__, no allocations) ----------------
__device__ int   g_deg[N_NODES];
__device__ int   g_rowptr[N_NODES + 1];
__device__ int   g_cursor[N_NODES];
__device__ int   g_col[N_EDGES];
__device__ float g_agg [(size_t)N_NODES * 256];
__device__ float g_bufA[(size_t)N_NODES * 256];
__device__ float g_bufB[(size_t)N_NODES * 256];
__device__ float g_stats[1152];   // [0..fout) = sum, [fout..2fout) = sumsq

// ---------------- CSR build ----------------
__global__ void k_zero_deg() {
    int i = blockIdx.x * blockDim.x + threadIdx.x;
    if (i < N_NODES) g_deg[i] = 0;
}

__global__ void k_count_deg(const int* __restrict__ dst) {
    int e = blockIdx.x * blockDim.x + threadIdx.x;
    if (e < N_EDGES) atomicAdd(&g_deg[dst[e]], 1);
}

// single-block exclusive scan of g_deg -> g_rowptr (+cursor copy)
__global__ void k_scan_deg() {
    __shared__ int sm[1024];
    __shared__ int carry;
    if (threadIdx.x == 0) carry = 0;
    __syncthreads();
    for (int base = 0; base < N_NODES; base += 1024) {
        int i = base + threadIdx.x;
        int v = (i < N_NODES) ? g_deg[i] : 0;
        sm[threadIdx.x] = v;
        __syncthreads();
        #pragma unroll
        for (int off = 1; off < 1024; off <<= 1) {
            int t = 0;
            if (threadIdx.x >= off) t = sm[threadIdx.x - off];
            __syncthreads();
            if (threadIdx.x >= off) sm[threadIdx.x] += t;
            __syncthreads();
        }
        int incl = sm[threadIdx.x];
        int excl = incl - v + carry;
        if (i < N_NODES) { g_rowptr[i] = excl; g_cursor[i] = excl; }
        __syncthreads();
        if (threadIdx.x == 1023) carry += sm[1023];
        __syncthreads();
    }
    if (threadIdx.x == 0) g_rowptr[N_NODES] = carry;
}

__global__ void k_fill_csr(const int* __restrict__ src, const int* __restrict__ dst) {
    int e = blockIdx.x * blockDim.x + threadIdx.x;
    if (e < N_EDGES) {
        int d = dst[e];
        int p = atomicAdd(&g_cursor[d], 1);
        g_col[p] = src[e];
    }
}

// ---------------- SpMM (mean aggregation), warp per node ----------------
template <int FIN>
__global__ void k_spmm_mean(const float* __restrict__ x) {
    int warp = (blockIdx.x * blockDim.x + threadIdx.x) >> 5;
    if (warp >= N_NODES) return;
    int lane = threadIdx.x & 31;
    int s = g_rowptr[warp];
    int e = g_rowptr[warp + 1];
    constexpr int NK = (FIN + 31) / 32;
    float acc[NK];
    #pragma unroll
    for (int k = 0; k < NK; k++) acc[k] = 0.f;

    int j = s;
    for (; j + 1 < e; j += 2) {
        int s0 = g_col[j];
        int s1 = g_col[j + 1];
        const float* r0 = x + (size_t)s0 * FIN;
        const float* r1 = x + (size_t)s1 * FIN;
        #pragma unroll
        for (int k = 0; k < NK; k++) {
            int c = k * 32 + lane;
            if (c < FIN) acc[k] += __ldg(r0 + c) + __ldg(r1 + c);
        }
    }
    if (j < e) {
        int s0 = g_col[j];
        const float* r0 = x + (size_t)s0 * FIN;
        #pragma unroll
        for (int k = 0; k < NK; k++) {
            int c = k * 32 + lane;
            if (c < FIN) acc[k] += __ldg(r0 + c);
        }
    }
    int d = e - s;
    float inv = 1.0f / (float)(d > 0 ? d : 1);
    float* out = g_agg + (size_t)warp * FIN;
    #pragma unroll
    for (int k = 0; k < NK; k++) {
        int c = k * 32 + lane;
        if (c < FIN) out[c] = acc[k] * inv;
    }
}

// ---------------- fused dual GEMM: out = A1*B1^T + A2*B2^T + bias ----------------
// A1 = agg [M,K], A2 = x [M,K], B1 = Wl [fout,K], B2 = Wr [fout,K] (row-major)
// block tile 128x64, thread tile 8x8, BK=16, 128 threads
template <int K>
__launch_bounds__(128, 4)
__global__ void k_gemm_dual(const float* __restrict__ A1, const float* __restrict__ A2,
                            const float* __restrict__ B1, const float* __restrict__ B2,
                            const float* __restrict__ bias, float* __restrict__ out,
                            int fout) {
    constexpr int BM = 128, BN = 64, BK = 16;
    constexpr int K2 = 2 * K;
    constexpr int NT = (K2 + BK - 1) / BK;
    constexpr int AST = BK + 4;   // 20 floats, keeps float4 alignment, kills store conflicts
    constexpr int BST = BN + 4;   // 68 floats

    __shared__ float As[BM * AST];
    __shared__ float Bs[BK * BST];

    int tid = threadIdx.x;
    int tx = tid & 7;     // col group: cols tx*8 .. tx*8+7
    int ty = tid >> 3;    // row group: rows ty*8 .. ty*8+7
    int m0 = blockIdx.x * BM;
    int n0 = blockIdx.y * BN;

    float4 pa[4];
    float4 pb[2];

    // A tile: 128 rows x 16 k = 512 float4; thread handles 4 (idx = tid + i*128)
    //   c = idx & 3 (k-offset 4c), m = idx >> 2
    // B tile: 64 rows x 16 k = 256 float4; thread handles 2
    auto loadA = [&](int kt) {
        int kbase = kt * BK;
        #pragma unroll
        for (int i = 0; i < 4; i++) {
            int idx = tid + i * 128;
            int c = idx & 3, m = idx >> 2;
            int k2 = kbase + c * 4;
            float4 v = make_float4(0.f, 0.f, 0.f, 0.f);
            int row = m0 + m;
            if (row < N_NODES && k2 < K2) {
                const float* srcp = (k2 < K) ? (A1 + (size_t)row * K + k2)
                                             : (A2 + (size_t)row * K + (k2 - K));
                v = *(const float4*)srcp;
            }
            pa[i] = v;
        }
    };
    auto loadB = [&](int kt) {
        int kbase = kt * BK;
        #pragma unroll
        for (int i = 0; i < 2; i++) {
            int idx = tid + i * 128;
            int c = idx & 3, o = idx >> 2;
            int k2 = kbase + c * 4;
            float4 v = make_float4(0.f, 0.f, 0.f, 0.f);
            if (k2 < K2) {
                int on = n0 + o;
                const float* srcp = (k2 < K) ? (B1 + (size_t)on * K + k2)
                                             : (B2 + (size_t)on * K + (k2 - K));
                v = *(const float4*)srcp;
            }
            pb[i] = v;
        }
    };
    auto storeA = [&]() {
        #pragma unroll
        for (int i = 0; i < 4; i++) {
            int idx = tid + i * 128;
            int c = idx & 3, m = idx >> 2;
            *(float4*)&As[m * AST + c * 4] = pa[i];
        }
    };
    auto storeB = [&]() {
        #pragma unroll
        for (int i = 0; i < 2; i++) {
            int idx = tid + i * 128;
            int c = idx & 3, o = idx >> 2;
            float v[4] = {pb[i].x, pb[i].y, pb[i].z, pb[i].w};
            #pragma unroll
            for (int q = 0; q < 4; q++) Bs[(c * 4 + q) * BST + o] = v[q];
        }
    };

    float acc[8][8];
    #pragma unroll
    for (int i = 0; i < 8; i++)
        #pragma unroll
        for (int j = 0; j < 8; j++) acc[i][j] = 0.f;

    loadA(0);
    loadB(0);
    for (int kt = 0; kt < NT; kt++) {
        __syncthreads();
        storeA();
        storeB();
        __syncthreads();
        if (kt + 1 < NT) { loadA(kt + 1); loadB(kt + 1); }
        #pragma unroll
        for (int kk = 0; kk < BK; kk++) {
            float a[8], b[8];
            #pragma unroll
            for (int i = 0; i < 8; i++) a[i] = As[(ty * 8 + i) * AST + kk];
            float4 b0 = *(float4*)&Bs[kk * BST + tx * 8];
            float4 b1 = *(float4*)&Bs[kk * BST + tx * 8 + 4];
            b[0] = b0.x; b[1] = b0.y; b[2] = b0.z; b[3] = b0.w;
            b[4] = b1.x; b[5] = b1.y; b[6] = b1.z; b[7] = b1.w;
            #pragma unroll
            for (int i = 0; i < 8; i++)
                #pragma unroll
                for (int j = 0; j < 8; j++)
                    acc[i][j] = fmaf(a[i], b[j], acc[i][j]);
        }
    }

    float bv[8];
    #pragma unroll
    for (int j = 0; j < 8; j++) bv[j] = bias[n0 + tx * 8 + j];

    #pragma unroll
    for (int i = 0; i < 8; i++) {
        int m = m0 + ty * 8 + i;
        if (m < N_NODES) {
            float* orow = out + (size_t)m * fout + n0 + tx * 8;
            float4 o0 = make_float4(acc[i][0] + bv[0], acc[i][1] + bv[1],
                                    acc[i][2] + bv[2], acc[i][3] + bv[3]);
            float4 o1 = make_float4(acc[i][4] + bv[4], acc[i][5] + bv[5],
                                    acc[i][6] + bv[6], acc[i][7] + bv[7]);
            *(float4*)orow = o0;
            *(float4*)(orow + 4) = o1;
        }
    }
}

// ---------------- BatchNorm ----------------
__global__ void k_zero_stats(int n2) {
    int i = blockIdx.x * blockDim.x + threadIdx.x;
    if (i < n2) g_stats[i] = 0.f;
}

__global__ void k_bn_reduce(const float* __restrict__ X, int fout) {
    __shared__ float s1[256], s2[256];
    int c = threadIdx.x & 63;
    int r = threadIdx.x >> 6;
    int col = blockIdx.y * 64 + c;
    float sum = 0.f, sq = 0.f;
    for (int m = blockIdx.x * 4 + r; m < N_NODES; m += gridDim.x * 4) {
        float v = X[(size_t)m * fout + col];
        sum += v;
        sq = fmaf(v, v, sq);
    }
    s1[threadIdx.x] = sum;
    s2[threadIdx.x] = sq;
    __syncthreads();
    if (r == 0) {
        sum = s1[c] + s1[c + 64] + s1[c + 128] + s1[c + 192];
        sq  = s2[c] + s2[c + 64] + s2[c + 128] + s2[c + 192];
        atomicAdd(&g_stats[col], sum);
        atomicAdd(&g_stats[fout + col], sq);
    }
}

// fout is a power of two (64/128/256) for all BN layers
__global__ void k_bn_apply(float* __restrict__ X, const float* __restrict__ gamma,
                           const float* __restrict__ beta, int fout) {
    const float invN = 1.0f / (float)N_NODES;
    int idx4 = blockIdx.x * blockDim.x + threadIdx.x;
    int total4 = N_NODES * fout / 4;
    if (idx4 >= total4) return;
    int c0 = (idx4 * 4) & (fout - 1);
    float4 v = *(float4*)(X + (size_t)idx4 * 4);
    float vv[4] = {v.x, v.y, v.z, v.w};
    #pragma unroll
    for (int q = 0; q < 4; q++) {
        int c = c0 + q;
        float m = g_stats[c] * invN;
        float var = g_stats[fout + c] * invN - m * m;
        float sc = rsqrtf(var + 1e-5f) * gamma[c];
        float y = (vv[q] - m) * sc + beta[c];
        vv[q] = fmaxf(y, 0.f);
    }
    *(float4*)(X + (size_t)idx4 * 4) = make_float4(vv[0], vv[1], vv[2], vv[3]);
}

// ---------------- driver ----------------
extern "C" void kernel_launch(void* const* d_in, const int* in_sizes, int n_in,
                              void* d_out, int out_size) {
    const float* x0  = (const float*)d_in[0];
    const int*   ei  = (const int*)d_in[1];
    const int*   srcp = ei;
    const int*   dstp = ei + N_EDGES;

    const float* Wl[5] = {(const float*)d_in[2], (const float*)d_in[5], (const float*)d_in[8],
                          (const float*)d_in[11], (const float*)d_in[14]};
    const float* Wr[5] = {(const float*)d_in[3], (const float*)d_in[6], (const float*)d_in[9],
                          (const float*)d_in[12], (const float*)d_in[15]};
    const float* bs[5] = {(const float*)d_in[4], (const float*)d_in[7], (const float*)d_in[10],
                          (const float*)d_in[13], (const float*)d_in[16]};
    const float* gm[4] = {(const float*)d_in[17], (const float*)d_in[19],
                          (const float*)d_in[21], (const float*)d_in[23]};
    const float* be[4] = {(const float*)d_in[18], (const float*)d_in[20],
                          (const float*)d_in[22], (const float*)d_in[24]};

    float *agg, *bufA, *bufB;
    cudaGetSymbolAddress((void**)&agg,  g_agg);
    cudaGetSymbolAddress((void**)&bufA, g_bufA);
    cudaGetSymbolAddress((void**)&bufB, g_bufB);
    float* outp = (float*)d_out;

    // ---- CSR build ----
    k_zero_deg<<<(N_NODES + 255) / 256, 256>>>();
    k_count_deg<<<(N_EDGES + 255) / 256, 256>>>(dstp);
    k_scan_deg<<<1, 1024>>>();
    k_fill_csr<<<(N_EDGES + 255) / 256, 256>>>(srcp, dstp);

    const int SPMM_BLOCKS = (N_NODES * 32 + 255) / 256;   // warp per node, 8 warps/block
    const int GX = (N_NODES + 127) / 128;

    // ---- layer 1: 196 -> 64 ----
    k_spmm_mean<196><<<SPMM_BLOCKS, 256>>>(x0);
    k_gemm_dual<196><<<dim3(GX, 1), 128>>>(agg, x0, Wl[0], Wr[0], bs[0], bufA, 64);
    k_zero_stats<<<1, 512>>>(128);
    k_bn_reduce<<<dim3(256, 1), 256>>>(bufA, 64);
    k_bn_apply<<<(N_NODES * 64 / 4 + 255) / 256, 256>>>(bufA, gm[0], be[0], 64);

    // ---- layer 2: 64 -> 128 ----
    k_spmm_mean<64><<<SPMM_BLOCKS, 256>>>(bufA);
    k_gemm_dual<64><<<dim3(GX, 2), 128>>>(agg, bufA, Wl[1], Wr[1], bs[1], bufB, 128);
    k_zero_stats<<<1, 512>>>(256);
    k_bn_reduce<<<dim3(256, 2), 256>>>(bufB, 128);
    k_bn_apply<<<(N_NODES * 128 / 4 + 255) / 256, 256>>>(bufB, gm[1], be[1], 128);

    // ---- layer 3: 128 -> 256 ----
    k_spmm_mean<128><<<SPMM_BLOCKS, 256>>>(bufB);
    k_gemm_dual<128><<<dim3(GX, 4), 128>>>(agg, bufB, Wl[2], Wr[2], bs[2], bufA, 256);
    k_zero_stats<<<1, 512>>>(512);
    k_bn_reduce<<<dim3(256, 4), 256>>>(bufA, 256);
    k_bn_apply<<<(N_NODES * 256 / 4 + 255) / 256, 256>>>(bufA, gm[2], be[2], 256);

    // ---- layer 4: 256 -> 256 ----
    k_spmm_mean<256><<<SPMM_BLOCKS, 256>>>(bufA);
    k_gemm_dual<256><<<dim3(GX, 4), 128>>>(agg, bufA, Wl[3], Wr[3], bs[3], bufB, 256);
    k_zero_stats<<<1, 512>>>(512);
    k_bn_reduce<<<dim3(256, 4), 256>>>(bufB, 256);
    k_bn_apply<<<(N_NODES * 256 / 4 + 255) / 256, 256>>>(bufB, gm[3], be[3], 256);

    // ---- layer 5: 256 -> 576 (no BN/relu), write to d_out ----
    k_spmm_mean<256><<<SPMM_BLOCKS, 256>>>(bufB);
    k_gemm_dual<256><<<dim3(GX, 9), 128>>>(agg, bufB, Wl[4], Wr[4], bs[4], outp, 576);
}

// round 15
// speedup vs baseline: 1.0025x; 1.0003x over previous
#include <cuda_runtime.h>

#define N_NODES 100000
#define N_EDGES 1600000

// ---------------- scratch (static __device__, no allocations) ----------------
__device__ int   g_deg[N_NODES];
__device__ int   g_rowptr[N_NODES + 1];
__device__ int   g_cursor[N_NODES];
__device__ int   g_col[N_EDGES];
__device__ float g_agg [(size_t)N_NODES * 256];
__device__ float g_bufA[(size_t)N_NODES * 256];
__device__ float g_bufB[(size_t)N_NODES * 256];
__device__ float g_stats[1152];   // [0..fout) = sum, [fout..2fout) = sumsq

// ---------------- CSR build ----------------
__global__ void k_zero_deg() {
    int i = blockIdx.x * blockDim.x + threadIdx.x;
    if (i < N_NODES) g_deg[i] = 0;
}

__global__ void k_count_deg(const int* __restrict__ dst) {
    int e = blockIdx.x * blockDim.x + threadIdx.x;
    if (e < N_EDGES) atomicAdd(&g_deg[dst[e]], 1);
}

// single-block exclusive scan of g_deg -> g_rowptr (+cursor copy)
__global__ void k_scan_deg() {
    __shared__ int sm[1024];
    __shared__ int carry;
    if (threadIdx.x == 0) carry = 0;
    __syncthreads();
    for (int base = 0; base < N_NODES; base += 1024) {
        int i = base + threadIdx.x;
        int v = (i < N_NODES) ? g_deg[i] : 0;
        sm[threadIdx.x] = v;
        __syncthreads();
        #pragma unroll
        for (int off = 1; off < 1024; off <<= 1) {
            int t = 0;
            if (threadIdx.x >= off) t = sm[threadIdx.x - off];
            __syncthreads();
            if (threadIdx.x >= off) sm[threadIdx.x] += t;
            __syncthreads();
        }
        int incl = sm[threadIdx.x];
        int excl = incl - v + carry;
        if (i < N_NODES) { g_rowptr[i] = excl; g_cursor[i] = excl; }
        __syncthreads();
        if (threadIdx.x == 1023) carry += sm[1023];
        __syncthreads();
    }
    if (threadIdx.x == 0) g_rowptr[N_NODES] = carry;
}

__global__ void k_fill_csr(const int* __restrict__ src, const int* __restrict__ dst) {
    int e = blockIdx.x * blockDim.x + threadIdx.x;
    if (e < N_EDGES) {
        int d = dst[e];
        int p = atomicAdd(&g_cursor[d], 1);
        g_col[p] = src[e];
    }
}

// ---------------- SpMM (mean aggregation), warp per node ----------------
template <int FIN>
__global__ void k_spmm_mean(const float* __restrict__ x) {
    int warp = (blockIdx.x * blockDim.x + threadIdx.x) >> 5;
    if (warp >= N_NODES) return;
    int lane = threadIdx.x & 31;
    int s = g_rowptr[warp];
    int e = g_rowptr[warp + 1];
    constexpr int NK = (FIN + 31) / 32;
    float acc[NK];
    #pragma unroll
    for (int k = 0; k < NK; k++) acc[k] = 0.f;

    int j = s;
    for (; j + 1 < e; j += 2) {
        int s0 = g_col[j];
        int s1 = g_col[j + 1];
        const float* r0 = x + (size_t)s0 * FIN;
        const float* r1 = x + (size_t)s1 * FIN;
        #pragma unroll
        for (int k = 0; k < NK; k++) {
            int c = k * 32 + lane;
            if (c < FIN) acc[k] += __ldg(r0 + c) + __ldg(r1 + c);
        }
    }
    if (j < e) {
        int s0 = g_col[j];
        const float* r0 = x + (size_t)s0 * FIN;
        #pragma unroll
        for (int k = 0; k < NK; k++) {
            int c = k * 32 + lane;
            if (c < FIN) acc[k] += __ldg(r0 + c);
        }
    }
    int d = e - s;
    float inv = 1.0f / (float)(d > 0 ? d : 1);
    float* out = g_agg + (size_t)warp * FIN;
    #pragma unroll
    for (int k = 0; k < NK; k++) {
        int c = k * 32 + lane;
        if (c < FIN) out[c] = acc[k] * inv;
    }
}

// ---------------- fused dual GEMM: out = A1*B1^T + A2*B2^T + bias ----------------
// A1 = agg [M,K], A2 = x [M,K], B1 = Wl [fout,K], B2 = Wr [fout,K] (row-major)
// block tile 128x64, thread tile 8x8, BK=16, 128 threads
template <int K>
__launch_bounds__(128, 4)
__global__ void k_gemm_dual(const float* __restrict__ A1, const float* __restrict__ A2,
                            const float* __restrict__ B1, const float* __restrict__ B2,
                            const float* __restrict__ bias, float* __restrict__ out,
                            int fout) {
    constexpr int BM = 128, BN = 64, BK = 16;
    constexpr int K2 = 2 * K;
    constexpr int NT = (K2 + BK - 1) / BK;
    constexpr int AST = BK + 4;   // 20 floats, keeps float4 alignment, kills store conflicts
    constexpr int BST = BN + 4;   // 68 floats

    __shared__ float As[BM * AST];
    __shared__ float Bs[BK * BST];

    int tid = threadIdx.x;
    int tx = tid & 7;     // col group: cols tx*8 .. tx*8+7
    int ty = tid >> 3;    // row group: rows ty*8 .. ty*8+7
    int m0 = blockIdx.x * BM;
    int n0 = blockIdx.y * BN;

    float4 pa[4];
    float4 pb[2];

    // A tile: 128 rows x 16 k = 512 float4; thread handles 4 (idx = tid + i*128)
    //   c = idx & 3 (k-offset 4c), m = idx >> 2
    // B tile: 64 rows x 16 k = 256 float4; thread handles 2
    auto loadA = [&](int kt) {
        int kbase = kt * BK;
        #pragma unroll
        for (int i = 0; i < 4; i++) {
            int idx = tid + i * 128;
            int c = idx & 3, m = idx >> 2;
            int k2 = kbase + c * 4;
            float4 v = make_float4(0.f, 0.f, 0.f, 0.f);
            int row = m0 + m;
            if (row < N_NODES && k2 < K2) {
                const float* srcp = (k2 < K) ? (A1 + (size_t)row * K + k2)
                                             : (A2 + (size_t)row * K + (k2 - K));
                v = *(const float4*)srcp;
            }
            pa[i] = v;
        }
    };
    auto loadB = [&](int kt) {
        int kbase = kt * BK;
        #pragma unroll
        for (int i = 0; i < 2; i++) {
            int idx = tid + i * 128;
            int c = idx & 3, o = idx >> 2;
            int k2 = kbase + c * 4;
            float4 v = make_float4(0.f, 0.f, 0.f, 0.f);
            if (k2 < K2) {
                int on = n0 + o;
                const float* srcp = (k2 < K) ? (B1 + (size_t)on * K + k2)
                                             : (B2 + (size_t)on * K + (k2 - K));
                v = *(const float4*)srcp;
            }
            pb[i] = v;
        }
    };
    auto storeA = [&]() {
        #pragma unroll
        for (int i = 0; i < 4; i++) {
            int idx = tid + i * 128;
            int c = idx & 3, m = idx >> 2;
            *(float4*)&As[m * AST + c * 4] = pa[i];
        }
    };
    auto storeB = [&]() {
        #pragma unroll
        for (int i = 0; i < 2; i++) {
            int idx = tid + i * 128;
            int c = idx & 3, o = idx >> 2;
            float v[4] = {pb[i].x, pb[i].y, pb[i].z, pb[i].w};
            #pragma unroll
            for (int q = 0; q < 4; q++) Bs[(c * 4 + q) * BST + o] = v[q];
        }
    };

    float acc[8][8];
    #pragma unroll
    for (int i = 0; i < 8; i++)
        #pragma unroll
        for (int j = 0; j < 8; j++) acc[i][j] = 0.f;

    loadA(0);
    loadB(0);
    for (int kt = 0; kt < NT; kt++) {
        __syncthreads();
        storeA();
        storeB();
        __syncthreads();
        if (kt + 1 < NT) { loadA(kt + 1); loadB(kt + 1); }
        #pragma unroll
        for (int kk = 0; kk < BK; kk++) {
            float a[8], b[8];
            #pragma unroll
            for (int i = 0; i < 8; i++) a[i] = As[(ty * 8 + i) * AST + kk];
            float4 b0 = *(float4*)&Bs[kk * BST + tx * 8];
            float4 b1 = *(float4*)&Bs[kk * BST + tx * 8 + 4];
            b[0] = b0.x; b[1] = b0.y; b[2] = b0.z; b[3] = b0.w;
            b[4] = b1.x; b[5] = b1.y; b[6] = b1.z; b[7] = b1.w;
            #pragma unroll
            for (int i = 0; i < 8; i++)
                #pragma unroll
                for (int j = 0; j < 8; j++)
                    acc[i][j] = fmaf(a[i], b[j], acc[i][j]);
        }
    }

    float bv[8];
    #pragma unroll
    for (int j = 0; j < 8; j++) bv[j] = bias[n0 + tx * 8 + j];

    #pragma unroll
    for (int i = 0; i < 8; i++) {
        int m = m0 + ty * 8 + i;
        if (m < N_NODES) {
            float* orow = out + (size_t)m * fout + n0 + tx * 8;
            float4 o0 = make_float4(acc[i][0] + bv[0], acc[i][1] + bv[1],
                                    acc[i][2] + bv[2], acc[i][3] + bv[3]);
            float4 o1 = make_float4(acc[i][4] + bv[4], acc[i][5] + bv[5],
                                    acc[i][6] + bv[6], acc[i][7] + bv[7]);
            *(float4*)orow = o0;
            *(float4*)(orow + 4) = o1;
        }
    }
}

// ---------------- BatchNorm ----------------
__global__ void k_zero_stats(int n2) {
    int i = blockIdx.x * blockDim.x + threadIdx.x;
    if (i < n2) g_stats[i] = 0.f;
}

__global__ void k_bn_reduce(const float* __restrict__ X, int fout) {
    __shared__ float s1[256], s2[256];
    int c = threadIdx.x & 63;
    int r = threadIdx.x >> 6;
    int col = blockIdx.y * 64 + c;
    float sum = 0.f, sq = 0.f;
    for (int m = blockIdx.x * 4 + r; m < N_NODES; m += gridDim.x * 4) {
        float v = X[(size_t)m * fout + col];
        sum += v;
        sq = fmaf(v, v, sq);
    }
    s1[threadIdx.x] = sum;
    s2[threadIdx.x] = sq;
    __syncthreads();
    if (r == 0) {
        sum = s1[c] + s1[c + 64] + s1[c + 128] + s1[c + 192];
        sq  = s2[c] + s2[c + 64] + s2[c + 128] + s2[c + 192];
        atomicAdd(&g_stats[col], sum);
        atomicAdd(&g_stats[fout + col], sq);
    }
}

// fout is a power of two (64/128/256) for all BN layers
__global__ void k_bn_apply(float* __restrict__ X, const float* __restrict__ gamma,
                           const float* __restrict__ beta, int fout) {
    const float invN = 1.0f / (float)N_NODES;
    int idx4 = blockIdx.x * blockDim.x + threadIdx.x;
    int total4 = N_NODES * fout / 4;
    if (idx4 >= total4) return;
    int c0 = (idx4 * 4) & (fout - 1);
    float4 v = *(float4*)(X + (size_t)idx4 * 4);
    float vv[4] = {v.x, v.y, v.z, v.w};
    #pragma unroll
    for (int q = 0; q < 4; q++) {
        int c = c0 + q;
        float m = g_stats[c] * invN;
        float var = g_stats[fout + c] * invN - m * m;
        float sc = rsqrtf(var + 1e-5f) * gamma[c];
        float y = (vv[q] - m) * sc + beta[c];
        vv[q] = fmaxf(y, 0.f);
    }
    *(float4*)(X + (size_t)idx4 * 4) = make_float4(vv[0], vv[1], vv[2], vv[3]);
}

// ---------------- driver ----------------
extern "C" void kernel_launch(void* const* d_in, const int* in_sizes, int n_in,
                              void* d_out, int out_size) {
    const float* x0  = (const float*)d_in[0];
    const int*   ei  = (const int*)d_in[1];
    const int*   srcp = ei;
    const int*   dstp = ei + N_EDGES;

    const float* Wl[5] = {(const float*)d_in[2], (const float*)d_in[5], (const float*)d_in[8],
                          (const float*)d_in[11], (const float*)d_in[14]};
    const float* Wr[5] = {(const float*)d_in[3], (const float*)d_in[6], (const float*)d_in[9],
                          (const float*)d_in[12], (const float*)d_in[15]};
    const float* bs[5] = {(const float*)d_in[4], (const float*)d_in[7], (const float*)d_in[10],
                          (const float*)d_in[13], (const float*)d_in[16]};
    const float* gm[4] = {(const float*)d_in[17], (const float*)d_in[19],
                          (const float*)d_in[21], (const float*)d_in[23]};
    const float* be[4] = {(const float*)d_in[18], (const float*)d_in[20],
                          (const float*)d_in[22], (const float*)d_in[24]};

    float *agg, *bufA, *bufB;
    cudaGetSymbolAddress((void**)&agg,  g_agg);
    cudaGetSymbolAddress((void**)&bufA, g_bufA);
    cudaGetSymbolAddress((void**)&bufB, g_bufB);
    float* outp = (float*)d_out;

    // ---- CSR build ----
    k_zero_deg<<<(N_NODES + 255) / 256, 256>>>();
    k_count_deg<<<(N_EDGES + 255) / 256, 256>>>(dstp);
    k_scan_deg<<<1, 1024>>>();
    k_fill_csr<<<(N_EDGES + 255) / 256, 256>>>(srcp, dstp);

    const int SPMM_BLOCKS = (N_NODES * 32 + 255) / 256;   // warp per node, 8 warps/block
    const int GX = (N_NODES + 127) / 128;

    // ---- layer 1: 196 -> 64 ----
    k_spmm_mean<196><<<SPMM_BLOCKS, 256>>>(x0);
    k_gemm_dual<196><<<dim3(GX, 1), 128>>>(agg, x0, Wl[0], Wr[0], bs[0], bufA, 64);
    k_zero_stats<<<1, 512>>>(128);
    k_bn_reduce<<<dim3(256, 1), 256>>>(bufA, 64);
    k_bn_apply<<<(N_NODES * 64 / 4 + 255) / 256, 256>>>(bufA, gm[0], be[0], 64);

    // ---- layer 2: 64 -> 128 ----
    k_spmm_mean<64><<<SPMM_BLOCKS, 256>>>(bufA);
    k_gemm_dual<64><<<dim3(GX, 2), 128>>>(agg, bufA, Wl[1], Wr[1], bs[1], bufB, 128);
    k_zero_stats<<<1, 512>>>(256);
    k_bn_reduce<<<dim3(256, 2), 256>>>(bufB, 128);
    k_bn_apply<<<(N_NODES * 128 / 4 + 255) / 256, 256>>>(bufB, gm[1], be[1], 128);

    // ---- layer 3: 128 -> 256 ----
    k_spmm_mean<128><<<SPMM_BLOCKS, 256>>>(bufB);
    k_gemm_dual<128><<<dim3(GX, 4), 128>>>(agg, bufB, Wl[2], Wr[2], bs[2], bufA, 256);
    k_zero_stats<<<1, 512>>>(512);
    k_bn_reduce<<<dim3(256, 4), 256>>>(bufA, 256);
    k_bn_apply<<<(N_NODES * 256 / 4 + 255) / 256, 256>>>(bufA, gm[2], be[2], 256);

    // ---- layer 4: 256 -> 256 ----
    k_spmm_mean<256><<<SPMM_BLOCKS, 256>>>(bufA);
    k_gemm_dual<256><<<dim3(GX, 4), 128>>>(agg, bufA, Wl[3], Wr[3], bs[3], bufB, 256);
    k_zero_stats<<<1, 512>>>(512);
    k_bn_reduce<<<dim3(256, 4), 256>>>(bufB, 256);
    k_bn_apply<<<(N_NODES * 256 / 4 + 255) / 256, 256>>>(bufB, gm[3], be[3], 256);

    // ---- layer 5: 256 -> 576 (no BN/relu), write to d_out ----
    k_spmm_mean<256><<<SPMM_BLOCKS, 256>>>(bufB);
    k_gemm_dual<256><<<dim3(GX, 9), 128>>>(agg, bufB, Wl[4], Wr[4], bs[4], outp, 576);
}

// round 16
// speedup vs baseline: 1.0034x; 1.0010x over previous
#include <cuda_runtime.h>

#define N_NODES 100000
#define N_EDGES 1600000

// ---------------- scratch (static __device__, no allocations) ----------------
__device__ int   g_deg[N_NODES];
__device__ int   g_rowptr[N_NODES + 1];
__device__ int   g_cursor[N_NODES];
__device__ int   g_col[N_EDGES];
__device__ float g_agg [(size_t)N_NODES * 256];
__device__ float g_bufA[(size_t)N_NODES * 256];
__device__ float g_bufB[(size_t)N_NODES * 256];
__device__ float g_stats[1152];   // [0..fout) = sum, [fout..2fout) = sumsq

// ---------------- CSR build ----------------
__global__ void k_zero_deg() {
    int i = blockIdx.x * blockDim.x + threadIdx.x;
    if (i < N_NODES) g_deg[i] = 0;
}

__global__ void k_count_deg(const int* __restrict__ dst) {
    int e = blockIdx.x * blockDim.x + threadIdx.x;
    if (e < N_EDGES) atomicAdd(&g_deg[dst[e]], 1);
}

// single-block exclusive scan of g_deg -> g_rowptr (+cursor copy)
__global__ void k_scan_deg() {
    __shared__ int sm[1024];
    __shared__ int carry;
    if (threadIdx.x == 0) carry = 0;
    __syncthreads();
    for (int base = 0; base < N_NODES; base += 1024) {
        int i = base + threadIdx.x;
        int v = (i < N_NODES) ? g_deg[i] : 0;
        sm[threadIdx.x] = v;
        __syncthreads();
        #pragma unroll
        for (int off = 1; off < 1024; off <<= 1) {
            int t = 0;
            if (threadIdx.x >= off) t = sm[threadIdx.x - off];
            __syncthreads();
            if (threadIdx.x >= off) sm[threadIdx.x] += t;
            __syncthreads();
        }
        int incl = sm[threadIdx.x];
        int excl = incl - v + carry;
        if (i < N_NODES) { g_rowptr[i] = excl; g_cursor[i] = excl; }
        __syncthreads();
        if (threadIdx.x == 1023) carry += sm[1023];
        __syncthreads();
    }
    if (threadIdx.x == 0) g_rowptr[N_NODES] = carry;
}

__global__ void k_fill_csr(const int* __restrict__ src, const int* __restrict__ dst) {
    int e = blockIdx.x * blockDim.x + threadIdx.x;
    if (e < N_EDGES) {
        int d = dst[e];
        int p = atomicAdd(&g_cursor[d], 1);
        g_col[p] = src[e];
    }
}

// ---------------- SpMM (mean aggregation), warp per node ----------------
template <int FIN>
__global__ void k_spmm_mean(const float* __restrict__ x) {
    int warp = (blockIdx.x * blockDim.x + threadIdx.x) >> 5;
    if (warp >= N_NODES) return;
    int lane = threadIdx.x & 31;
    int s = g_rowptr[warp];
    int e = g_rowptr[warp + 1];
    constexpr int NK = (FIN + 31) / 32;
    float acc[NK];
    #pragma unroll
    for (int k = 0; k < NK; k++) acc[k] = 0.f;

    int j = s;
    for (; j + 1 < e; j += 2) {
        int s0 = g_col[j];
        int s1 = g_col[j + 1];
        const float* r0 = x + (size_t)s0 * FIN;
        const float* r1 = x + (size_t)s1 * FIN;
        #pragma unroll
        for (int k = 0; k < NK; k++) {
            int c = k * 32 + lane;
            if (c < FIN) acc[k] += __ldg(r0 + c) + __ldg(r1 + c);
        }
    }
    if (j < e) {
        int s0 = g_col[j];
        const float* r0 = x + (size_t)s0 * FIN;
        #pragma unroll
        for (int k = 0; k < NK; k++) {
            int c = k * 32 + lane;
            if (c < FIN) acc[k] += __ldg(r0 + c);
        }
    }
    int d = e - s;
    float inv = 1.0f / (float)(d > 0 ? d : 1);
    float* out = g_agg + (size_t)warp * FIN;
    #pragma unroll
    for (int k = 0; k < NK; k++) {
        int c = k * 32 + lane;
        if (c < FIN) out[c] = acc[k] * inv;
    }
}

// ---------------- fused dual GEMM: out = A1*B1^T + A2*B2^T + bias ----------------
// A1 = agg [M,K], A2 = x [M,K], B1 = Wl [fout,K], B2 = Wr [fout,K] (row-major)
// block tile 128x64, thread tile 8x8, BK=16, 128 threads
template <int K>
__launch_bounds__(128, 4)
__global__ void k_gemm_dual(const float* __restrict__ A1, const float* __restrict__ A2,
                            const float* __restrict__ B1, const float* __restrict__ B2,
                            const float* __restrict__ bias, float* __restrict__ out,
                            int fout) {
    constexpr int BM = 128, BN = 64, BK = 16;
    constexpr int K2 = 2 * K;
    constexpr int NT = (K2 + BK - 1) / BK;
    constexpr int AST = BK + 4;   // 20 floats, keeps float4 alignment, kills store conflicts
    constexpr int BST = BN + 4;   // 68 floats

    __shared__ float As[BM * AST];
    __shared__ float Bs[BK * BST];

    int tid = threadIdx.x;
    int tx = tid & 7;     // col group: cols tx*8 .. tx*8+7
    int ty = tid >> 3;    // row group: rows ty*8 .. ty*8+7
    int m0 = blockIdx.x * BM;
    int n0 = blockIdx.y * BN;

    float4 pa[4];
    float4 pb[2];

    // A tile: 128 rows x 16 k = 512 float4; thread handles 4 (idx = tid + i*128)
    //   c = idx & 3 (k-offset 4c), m = idx >> 2
    // B tile: 64 rows x 16 k = 256 float4; thread handles 2
    auto loadA = [&](int kt) {
        int kbase = kt * BK;
        #pragma unroll
        for (int i = 0; i < 4; i++) {
            int idx = tid + i * 128;
            int c = idx & 3, m = idx >> 2;
            int k2 = kbase + c * 4;
            float4 v = make_float4(0.f, 0.f, 0.f, 0.f);
            int row = m0 + m;
            if (row < N_NODES && k2 < K2) {
                const float* srcp = (k2 < K) ? (A1 + (size_t)row * K + k2)
                                             : (A2 + (size_t)row * K + (k2 - K));
                v = *(const float4*)srcp;
            }
            pa[i] = v;
        }
    };
    auto loadB = [&](int kt) {
        int kbase = kt * BK;
        #pragma unroll
        for (int i = 0; i < 2; i++) {
            int idx = tid + i * 128;
            int c = idx & 3, o = idx >> 2;
            int k2 = kbase + c * 4;
            float4 v = make_float4(0.f, 0.f, 0.f, 0.f);
            if (k2 < K2) {
                int on = n0 + o;
                const float* srcp = (k2 < K) ? (B1 + (size_t)on * K + k2)
                                             : (B2 + (size_t)on * K + (k2 - K));
                v = *(const float4*)srcp;
            }
            pb[i] = v;
        }
    };
    auto storeA = [&]() {
        #pragma unroll
        for (int i = 0; i < 4; i++) {
            int idx = tid + i * 128;
            int c = idx & 3, m = idx >> 2;
            *(float4*)&As[m * AST + c * 4] = pa[i];
        }
    };
    auto storeB = [&]() {
        #pragma unroll
        for (int i = 0; i < 2; i++) {
            int idx = tid + i * 128;
            int c = idx & 3, o = idx >> 2;
            float v[4] = {pb[i].x, pb[i].y, pb[i].z, pb[i].w};
            #pragma unroll
            for (int q = 0; q < 4; q++) Bs[(c * 4 + q) * BST + o] = v[q];
        }
    };

    float acc[8][8];
    #pragma unroll
    for (int i = 0; i < 8; i++)
        #pragma unroll
        for (int j = 0; j < 8; j++) acc[i][j] = 0.f;

    loadA(0);
    loadB(0);
    for (int kt = 0; kt < NT; kt++) {
        __syncthreads();
        storeA();
        storeB();
        __syncthreads();
        if (kt + 1 < NT) { loadA(kt + 1); loadB(kt + 1); }
        #pragma unroll
        for (int kk = 0; kk < BK; kk++) {
            float a[8], b[8];
            #pragma unroll
            for (int i = 0; i < 8; i++) a[i] = As[(ty * 8 + i) * AST + kk];
            float4 b0 = *(float4*)&Bs[kk * BST + tx * 8];
            float4 b1 = *(float4*)&Bs[kk * BST + tx * 8 + 4];
            b[0] = b0.x; b[1] = b0.y; b[2] = b0.z; b[3] = b0.w;
            b[4] = b1.x; b[5] = b1.y; b[6] = b1.z; b[7] = b1.w;
            #pragma unroll
            for (int i = 0; i < 8; i++)
                #pragma unroll
                for (int j = 0; j < 8; j++)
                    acc[i][j] = fmaf(a[i], b[j], acc[i][j]);
        }
    }

    float bv[8];
    #pragma unroll
    for (int j = 0; j < 8; j++) bv[j] = bias[n0 + tx * 8 + j];

    #pragma unroll
    for (int i = 0; i < 8; i++) {
        int m = m0 + ty * 8 + i;
        if (m < N_NODES) {
            float* orow = out + (size_t)m * fout + n0 + tx * 8;
            float4 o0 = make_float4(acc[i][0] + bv[0], acc[i][1] + bv[1],
                                    acc[i][2] + bv[2], acc[i][3] + bv[3]);
            float4 o1 = make_float4(acc[i][4] + bv[4], acc[i][5] + bv[5],
                                    acc[i][6] + bv[6], acc[i][7] + bv[7]);
            *(float4*)orow = o0;
            *(float4*)(orow + 4) = o1;
        }
    }
}

// ---------------- BatchNorm ----------------
__global__ void k_zero_stats(int n2) {
    int i = blockIdx.x * blockDim.x + threadIdx.x;
    if (i < n2) g_stats[i] = 0.f;
}

__global__ void k_bn_reduce(const float* __restrict__ X, int fout) {
    __shared__ float s1[256], s2[256];
    int c = threadIdx.x & 63;
    int r = threadIdx.x >> 6;
    int col = blockIdx.y * 64 + c;
    float sum = 0.f, sq = 0.f;
    for (int m = blockIdx.x * 4 + r; m < N_NODES; m += gridDim.x * 4) {
        float v = X[(size_t)m * fout + col];
        sum += v;
        sq = fmaf(v, v, sq);
    }
    s1[threadIdx.x] = sum;
    s2[threadIdx.x] = sq;
    __syncthreads();
    if (r == 0) {
        sum = s1[c] + s1[c + 64] + s1[c + 128] + s1[c + 192];
        sq  = s2[c] + s2[c + 64] + s2[c + 128] + s2[c + 192];
        atomicAdd(&g_stats[col], sum);
        atomicAdd(&g_stats[fout + col], sq);
    }
}

// fout is a power of two (64/128/256) for all BN layers
__global__ void k_bn_apply(float* __restrict__ X, const float* __restrict__ gamma,
                           const float* __restrict__ beta, int fout) {
    const float invN = 1.0f / (float)N_NODES;
    int idx4 = blockIdx.x * blockDim.x + threadIdx.x;
    int total4 = N_NODES * fout / 4;
    if (idx4 >= total4) return;
    int c0 = (idx4 * 4) & (fout - 1);
    float4 v = *(float4*)(X + (size_t)idx4 * 4);
    float vv[4] = {v.x, v.y, v.z, v.w};
    #pragma unroll
    for (int q = 0; q < 4; q++) {
        int c = c0 + q;
        float m = g_stats[c] * invN;
        float var = g_stats[fout + c] * invN - m * m;
        float sc = rsqrtf(var + 1e-5f) * gamma[c];
        float y = (vv[q] - m) * sc + beta[c];
        vv[q] = fmaxf(y, 0.f);
    }
    *(float4*)(X + (size_t)idx4 * 4) = make_float4(vv[0], vv[1], vv[2], vv[3]);
}

// ---------------- driver ----------------
extern "C" void kernel_launch(void* const* d_in, const int* in_sizes, int n_in,
                              void* d_out, int out_size) {
    const float* x0  = (const float*)d_in[0];
    const int*   ei  = (const int*)d_in[1];
    const int*   srcp = ei;
    const int*   dstp = ei + N_EDGES;

    const float* Wl[5] = {(const float*)d_in[2], (const float*)d_in[5], (const float*)d_in[8],
                          (const float*)d_in[11], (const float*)d_in[14]};
    const float* Wr[5] = {(const float*)d_in[3], (const float*)d_in[6], (const float*)d_in[9],
                          (const float*)d_in[12], (const float*)d_in[15]};
    const float* bs[5] = {(const float*)d_in[4], (const float*)d_in[7], (const float*)d_in[10],
                          (const float*)d_in[13], (const float*)d_in[16]};
    const float* gm[4] = {(const float*)d_in[17], (const float*)d_in[19],
                          (const float*)d_in[21], (const float*)d_in[23]};
    const float* be[4] = {(const float*)d_in[18], (const float*)d_in[20],
                          (const float*)d_in[22], (const float*)d_in[24]};

    float *agg, *bufA, *bufB;
    cudaGetSymbolAddress((void**)&agg,  g_agg);
    cudaGetSymbolAddress((void**)&bufA, g_bufA);
    cudaGetSymbolAddress((void**)&bufB, g_bufB);
    float* outp = (float*)d_out;

    // ---- CSR build ----
    k_zero_deg<<<(N_NODES + 255) / 256, 256>>>();
    k_count_deg<<<(N_EDGES + 255) / 256, 256>>>(dstp);
    k_scan_deg<<<1, 1024>>>();
    k_fill_csr<<<(N_EDGES + 255) / 256, 256>>>(srcp, dstp);

    const int SPMM_BLOCKS = (N_NODES * 32 + 255) / 256;   // warp per node, 8 warps/block
    const int GX = (N_NODES + 127) / 128;

    // ---- layer 1: 196 -> 64 ----
    k_spmm_mean<196><<<SPMM_BLOCKS, 256>>>(x0);
    k_gemm_dual<196><<<dim3(GX, 1), 128>>>(agg, x0, Wl[0], Wr[0], bs[0], bufA, 64);
    k_zero_stats<<<1, 512>>>(128);
    k_bn_reduce<<<dim3(256, 1), 256>>>(bufA, 64);
    k_bn_apply<<<(N_NODES * 64 / 4 + 255) / 256, 256>>>(bufA, gm[0], be[0], 64);

    // ---- layer 2: 64 -> 128 ----
    k_spmm_mean<64><<<SPMM_BLOCKS, 256>>>(bufA);
    k_gemm_dual<64><<<dim3(GX, 2), 128>>>(agg, bufA, Wl[1], Wr[1], bs[1], bufB, 128);
    k_zero_stats<<<1, 512>>>(256);
    k_bn_reduce<<<dim3(256, 2), 256>>>(bufB, 128);
    k_bn_apply<<<(N_NODES * 128 / 4 + 255) / 256, 256>>>(bufB, gm[1], be[1], 128);

    // ---- layer 3: 128 -> 256 ----
    k_spmm_mean<128><<<SPMM_BLOCKS, 256>>>(bufB);
    k_gemm_dual<128><<<dim3(GX, 4), 128>>>(agg, bufB, Wl[2], Wr[2], bs[2], bufA, 256);
    k_zero_stats<<<1, 512>>>(512);
    k_bn_reduce<<<dim3(256, 4), 256>>>(bufA, 256);
    k_bn_apply<<<(N_NODES * 256 / 4 + 255) / 256, 256>>>(bufA, gm[2], be[2], 256);

    // ---- layer 4: 256 -> 256 ----
    k_spmm_mean<256><<<SPMM_BLOCKS, 256>>>(bufA);
    k_gemm_dual<256><<<dim3(GX, 4), 128>>>(agg, bufA, Wl[3], Wr[3], bs[3], bufB, 256);
    k_zero_stats<<<1, 512>>>(512);
    k_bn_reduce<<<dim3(256, 4), 256>>>(bufB, 256);
    k_bn_apply<<<(N_NODES * 256 / 4 + 255) / 256, 256>>>(bufB, gm[3], be[3], 256);

    // ---- layer 5: 256 -> 576 (no BN/relu), write to d_out ----
    k_spmm_mean<256><<<SPMM_BLOCKS, 256>>>(bufB);
    k_gemm_dual<256><<<dim3(GX, 9), 128>>>(agg, bufB, Wl[4], Wr[4], bs[4], outp, 576);
}